// round 16
// baseline (speedup 1.0000x reference)
#include <cuda_runtime.h>
#include <math.h>

#define NN 100000
#define NE 1600000
#define D 128
#define H 64
#define SCAN_B 256
#define NBLK ((NN + SCAN_B - 1) / SCAN_B)   // 391

// ---------------- scratch (device globals) ----------------
__device__ float g_h[NN * H];
__device__ float g_z[NN * H];
__device__ float g_zs[NN];
__device__ float g_zd[NN];
__device__ float g_deg[NN];
__device__ float g_infl[NN];
__device__ unsigned int g_stat[2];
__device__ int g_cnt[NN];
__device__ int g_offs[NN + 1];
__device__ int g_cur[NN];
__device__ int g_csr[NE];
__device__ int g_bsum[512];

// ---------------- packed fp32x2 helpers ----------------
__device__ __forceinline__ unsigned long long ffma2(unsigned long long a,
                                                    unsigned long long b,
                                                    unsigned long long c) {
    unsigned long long d;
    asm("fma.rn.f32x2 %0, %1, %2, %3;" : "=l"(d) : "l"(a), "l"(b), "l"(c));
    return d;
}
__device__ __forceinline__ unsigned long long pk2(float x) {
    unsigned long long r;
    asm("mov.b64 %0, {%1, %1};" : "=l"(r) : "f"(x));
    return r;
}
__device__ __forceinline__ float2 up2(unsigned long long v) {
    float2 f;
    asm("mov.b64 {%0, %1}, %2;" : "=f"(f.x), "=f"(f.y) : "l"(v));
    return f;
}
__device__ __forceinline__ void st_relu4(float* p, unsigned long long ax,
                                         unsigned long long ay) {
    float2 u = up2(ax), v = up2(ay);
    p[0] = fmaxf(u.x, 0.f); p[1] = fmaxf(u.y, 0.f);
    p[2] = fmaxf(v.x, 0.f); p[3] = fmaxf(v.y, 0.f);
}

// ---------------- K0: feature attention + projection (R11 version) ------
template <int NODES>
__global__ void __launch_bounds__(128, 4) k_feat(
        int base,
        const float* __restrict__ x,
        const float* __restrict__ W1, const float* __restrict__ b1,
        const float* __restrict__ W2, const float* __restrict__ b2,
        const float* __restrict__ Wp, const float* __restrict__ bp) {
    constexpr int R = NODES / 8;           // rows per thread
    __shared__ float sx[NODES * 128];
    __shared__ float st[NODES * 64];
    int tid = threadIdx.x;
    int nodeBase = base + blockIdx.x * NODES;

    const float4* xg = (const float4*)(x + (size_t)nodeBase * 128);
    float4* sxv = (float4*)sx;
#pragma unroll
    for (int i = 0; i < NODES / 4; i++) sxv[tid + i * 128] = xg[tid + i * 128];
    __syncthreads();

    int g = tid >> 4;
    int l = tid & 15;

    // ---- stage 1: t = relu(x @ W1 + b1)   [K=128 -> O=64]
    {
        ulonglong2 bb = *(const ulonglong2*)(b1 + 4 * l);
        unsigned long long acc[R][2];
#pragma unroll
        for (int n = 0; n < R; n++) { acc[n][0] = bb.x; acc[n][1] = bb.y; }
#pragma unroll 2
        for (int k2 = 0; k2 < 128; k2 += 2) {
            float2 xv[R];
#pragma unroll
            for (int n = 0; n < R; n++)
                xv[n] = *(const float2*)(sx + (g + 8 * n) * 128 + k2);
            ulonglong2 w0 = *(const ulonglong2*)(W1 + k2 * 64 + 4 * l);
            ulonglong2 w1 = *(const ulonglong2*)(W1 + (k2 + 1) * 64 + 4 * l);
#pragma unroll
            for (int n = 0; n < R; n++) {
                unsigned long long a = pk2(xv[n].x), b = pk2(xv[n].y);
                acc[n][0] = ffma2(a, w0.x, acc[n][0]);
                acc[n][1] = ffma2(a, w0.y, acc[n][1]);
                acc[n][0] = ffma2(b, w1.x, acc[n][0]);
                acc[n][1] = ffma2(b, w1.y, acc[n][1]);
            }
        }
#pragma unroll
        for (int n = 0; n < R; n++)
            st_relu4(st + (g + 8 * n) * 64 + 4 * l, acc[n][0], acc[n][1]);
    }
    __syncthreads();

    // ---- stage 2: a = t @ W2 + b2  [K=64 -> O=128]; x *= sigmoid(a)
#pragma unroll
    for (int c = 0; c < R; c += 4) {
        ulonglong2 c0 = *(const ulonglong2*)(b2 + 8 * l);
        ulonglong2 c1 = *(const ulonglong2*)(b2 + 8 * l + 4);
        unsigned long long A[4][4];
#pragma unroll
        for (int n = 0; n < 4; n++) {
            A[n][0] = c0.x; A[n][1] = c0.y; A[n][2] = c1.x; A[n][3] = c1.y;
        }
#pragma unroll 2
        for (int k2 = 0; k2 < 64; k2 += 2) {
            float2 tv[4];
#pragma unroll
            for (int n = 0; n < 4; n++)
                tv[n] = *(const float2*)(st + (g + 8 * (c + n)) * 64 + k2);
            ulonglong2 wa0 = *(const ulonglong2*)(W2 + k2 * 128 + 8 * l);
            ulonglong2 wb0 = *(const ulonglong2*)(W2 + k2 * 128 + 8 * l + 4);
            ulonglong2 wa1 = *(const ulonglong2*)(W2 + (k2 + 1) * 128 + 8 * l);
            ulonglong2 wb1 = *(const ulonglong2*)(W2 + (k2 + 1) * 128 + 8 * l + 4);
#pragma unroll
            for (int n = 0; n < 4; n++) {
                unsigned long long a = pk2(tv[n].x), b = pk2(tv[n].y);
                A[n][0] = ffma2(a, wa0.x, A[n][0]); A[n][1] = ffma2(a, wa0.y, A[n][1]);
                A[n][2] = ffma2(a, wb0.x, A[n][2]); A[n][3] = ffma2(a, wb0.y, A[n][3]);
                A[n][0] = ffma2(b, wa1.x, A[n][0]); A[n][1] = ffma2(b, wa1.y, A[n][1]);
                A[n][2] = ffma2(b, wb1.x, A[n][2]); A[n][3] = ffma2(b, wb1.y, A[n][3]);
            }
        }
#pragma unroll
        for (int n = 0; n < 4; n++) {
            float* row = sx + (g + 8 * (c + n)) * 128 + 8 * l;
            float av[8];
            float2 p;
            p = up2(A[n][0]); av[0] = p.x; av[1] = p.y;
            p = up2(A[n][1]); av[2] = p.x; av[3] = p.y;
            p = up2(A[n][2]); av[4] = p.x; av[5] = p.y;
            p = up2(A[n][3]); av[6] = p.x; av[7] = p.y;
#pragma unroll
            for (int j = 0; j < 8; j++) row[j] *= 1.f / (1.f + __expf(-av[j]));
        }
    }
    __syncthreads();

    // ---- stage 3: h = xf @ Wp + bp  [K=128 -> O=64]
    {
        ulonglong2 bb = *(const ulonglong2*)(bp + 4 * l);
        unsigned long long acc[R][2];
#pragma unroll
        for (int n = 0; n < R; n++) { acc[n][0] = bb.x; acc[n][1] = bb.y; }
#pragma unroll 2
        for (int k2 = 0; k2 < 128; k2 += 2) {
            float2 xv[R];
#pragma unroll
            for (int n = 0; n < R; n++)
                xv[n] = *(const float2*)(sx + (g + 8 * n) * 128 + k2);
            ulonglong2 w0 = *(const ulonglong2*)(Wp + k2 * 64 + 4 * l);
            ulonglong2 w1 = *(const ulonglong2*)(Wp + (k2 + 1) * 64 + 4 * l);
#pragma unroll
            for (int n = 0; n < R; n++) {
                unsigned long long a = pk2(xv[n].x), b = pk2(xv[n].y);
                acc[n][0] = ffma2(a, w0.x, acc[n][0]);
                acc[n][1] = ffma2(a, w0.y, acc[n][1]);
                acc[n][0] = ffma2(b, w1.x, acc[n][0]);
                acc[n][1] = ffma2(b, w1.y, acc[n][1]);
            }
        }
#pragma unroll
        for (int n = 0; n < R; n++) {
            ulonglong2* h = (ulonglong2*)(g_h + (size_t)(nodeBase + g + 8 * n) * 64 + 4 * l);
            h->x = acc[n][0]; h->y = acc[n][1];
        }
    }
}

// ---------------- CSR build ----------------
__global__ void k_zero() {
    int i = blockIdx.x * blockDim.x + threadIdx.x;
    if (i < NN) { g_cnt[i] = 0; g_deg[i] = 0.f; g_infl[i] = 0.f; }
    if (i < 2) g_stat[i] = 0u;
}
__global__ void k_hist(const int* __restrict__ src, const int* __restrict__ dst) {
    int i = blockIdx.x * blockDim.x + threadIdx.x;
    if (i >= NE) return;
    atomicAdd(&g_cnt[dst[i]], 1);
    atomicAdd(&g_deg[src[i]], 1.f);
}
__global__ void k_scan1() {
    __shared__ int sh[SCAN_B];
    __shared__ float sm[SCAN_B];
    int i = blockIdx.x * SCAN_B + threadIdx.x;
    int v = (i < NN) ? g_cnt[i] : 0;
    sm[threadIdx.x] = (i < NN) ? g_deg[i] : 0.f;
    sh[threadIdx.x] = v;
    __syncthreads();
    for (int off = 1; off < SCAN_B; off <<= 1) {
        int add = (threadIdx.x >= off) ? sh[threadIdx.x - off] : 0;
        __syncthreads();
        sh[threadIdx.x] += add;
        __syncthreads();
    }
    if (i < NN) g_offs[i + 1] = sh[threadIdx.x];
    if (threadIdx.x == SCAN_B - 1) g_bsum[blockIdx.x] = sh[threadIdx.x];
    for (int s = 128; s > 0; s >>= 1) {
        if (threadIdx.x < s) sm[threadIdx.x] = fmaxf(sm[threadIdx.x], sm[threadIdx.x + s]);
        __syncthreads();
    }
    if (threadIdx.x == 0) atomicMax(&g_stat[0], __float_as_uint(sm[0]));
}
__global__ void k_scan2() {
    __shared__ int sh[512];
    int t = threadIdx.x;
    sh[t] = (t < NBLK) ? g_bsum[t] : 0;
    __syncthreads();
    for (int off = 1; off < 512; off <<= 1) {
        int add = (t >= off) ? sh[t - off] : 0;
        __syncthreads();
        sh[t] += add;
        __syncthreads();
    }
    if (t < NBLK) g_bsum[t] = sh[t];
}
__global__ void k_scan3() {
    int i = blockIdx.x * SCAN_B + threadIdx.x;
    if (i >= NN) return;
    int blk = blockIdx.x;
    int pre = (blk > 0) ? g_bsum[blk - 1] : 0;
    int inc = g_offs[i + 1] + pre;
    g_offs[i + 1] = inc;
    g_cur[i] = inc - g_cnt[i];
    if (i == 0) g_offs[0] = 0;
}
__global__ void k_scatter(const int* __restrict__ src, const int* __restrict__ dst) {
    int i = blockIdx.x * blockDim.x + threadIdx.x;
    if (i >= NE) return;
    int s = src[i];
    int d = dst[i];
    int pos = atomicAdd(&g_cur[d], 1);
    g_csr[pos] = s;
    atomicAdd(&g_infl[s], g_deg[d]);
}

// ---------------- K1: z = h @ W, zs, zd — templated R=NODES/8 -----------
template <int NODES>
__global__ void __launch_bounds__(128) k_zproj(
        int base,
        const float* __restrict__ W,
        const float* __restrict__ asrc,
        const float* __restrict__ adst) {
    constexpr int R = NODES / 8;
    __shared__ float sh[NODES * 64];
    __shared__ float sa[64], sd[64];
    int tid = threadIdx.x;
    int nodeBase = base + blockIdx.x * NODES;
    const float4* hg = (const float4*)(g_h + (size_t)nodeBase * 64);
#pragma unroll
    for (int i = 0; i < NODES / 8; i++) ((float4*)sh)[tid + i * 128] = hg[tid + i * 128];
    if (tid < 64) { sa[tid] = asrc[tid]; sd[tid] = adst[tid]; }
    __syncthreads();

    int g = tid >> 4;
    int l = tid & 15;
    unsigned long long acc[R][2];
#pragma unroll
    for (int n = 0; n < R; n++) { acc[n][0] = 0; acc[n][1] = 0; }
#pragma unroll 2
    for (int k2 = 0; k2 < 64; k2 += 2) {
        float2 hv[R];
#pragma unroll
        for (int n = 0; n < R; n++)
            hv[n] = *(const float2*)(sh + (g + 8 * n) * 64 + k2);
        ulonglong2 w0 = *(const ulonglong2*)(W + k2 * 64 + 4 * l);
        ulonglong2 w1 = *(const ulonglong2*)(W + (k2 + 1) * 64 + 4 * l);
#pragma unroll
        for (int n = 0; n < R; n++) {
            unsigned long long a = pk2(hv[n].x), b = pk2(hv[n].y);
            acc[n][0] = ffma2(a, w0.x, acc[n][0]);
            acc[n][1] = ffma2(a, w0.y, acc[n][1]);
            acc[n][0] = ffma2(b, w1.x, acc[n][0]);
            acc[n][1] = ffma2(b, w1.y, acc[n][1]);
        }
    }
    int c = 4 * l;
    float4 va = make_float4(sa[c], sa[c + 1], sa[c + 2], sa[c + 3]);
    float4 vd = make_float4(sd[c], sd[c + 1], sd[c + 2], sd[c + 3]);
    float s[R], dsum[R];
#pragma unroll
    for (int n = 0; n < R; n++) {
        int node = nodeBase + g + 8 * n;
        ulonglong2* z = (ulonglong2*)(g_z + (size_t)node * 64 + 4 * l);
        z->x = acc[n][0]; z->y = acc[n][1];
        float2 p = up2(acc[n][0]), q = up2(acc[n][1]);
        s[n]    = p.x * va.x + p.y * va.y + q.x * va.z + q.y * va.w;
        dsum[n] = p.x * vd.x + p.y * vd.y + q.x * vd.z + q.y * vd.w;
    }
#pragma unroll
    for (int o = 8; o > 0; o >>= 1) {
#pragma unroll
        for (int n = 0; n < R; n++) {
            s[n]    += __shfl_down_sync(0xffffffffu, s[n], o, 16);
            dsum[n] += __shfl_down_sync(0xffffffffu, dsum[n], o, 16);
        }
    }
    if (l == 0) {
#pragma unroll
        for (int n = 0; n < R; n++) {
            int node = nodeBase + g + 8 * n;
            g_zs[node] = s[n];
            g_zd[node] = dsum[n];
        }
    }
}

// ---------------- K2: fused GAT layer — single pass, unroll-by-2 --------
__global__ void k_gat(const float* __restrict__ b, const float* __restrict__ gamma,
                      const float* __restrict__ beta, const float* __restrict__ mean,
                      const float* __restrict__ var) {
    int node = (blockIdx.x * blockDim.x + threadIdx.x) >> 5;
    int lane = threadIdx.x & 31;
    if (node >= NN) return;

    int beg = g_offs[node];
    int end = g_offs[node + 1];
    float zdn = g_zd[node];

    float es = g_zs[node] + zdn;
    es = (es > 0.f) ? es : 0.2f * es;
    float exs = __expf(es);
    float den = exs;
    float2 zv = ((const float2*)(g_z + (size_t)node * 64))[lane];
    float2 acc = make_float2(exs * zv.x, exs * zv.y);

    for (int base = beg; base < end; base += 32) {
        int j = base + lane;
        float ex = 0.f;
        int s = 0;
        if (j < end) {
            s = g_csr[j];
            float e = g_zs[s] + zdn;
            e = (e > 0.f) ? e : 0.2f * e;
            ex = __expf(e);
        }
        int nk = min(32, end - base);
        int k = 0;
        for (; k + 1 < nk; k += 2) {
            float ex0 = __shfl_sync(0xffffffffu, ex, k);
            float ex1 = __shfl_sync(0xffffffffu, ex, k + 1);
            int s0 = __shfl_sync(0xffffffffu, s, k);
            int s1 = __shfl_sync(0xffffffffu, s, k + 1);
            float2 z0 = ((const float2*)(g_z + (size_t)s0 * 64))[lane];
            float2 z1 = ((const float2*)(g_z + (size_t)s1 * 64))[lane];
            den += ex0;
            acc.x = fmaf(ex0, z0.x, acc.x);
            acc.y = fmaf(ex0, z0.y, acc.y);
            den += ex1;
            acc.x = fmaf(ex1, z1.x, acc.x);
            acc.y = fmaf(ex1, z1.y, acc.y);
        }
        if (k < nk) {
            float exk = __shfl_sync(0xffffffffu, ex, k);
            int sk = __shfl_sync(0xffffffffu, s, k);
            float2 zr = ((const float2*)(g_z + (size_t)sk * 64))[lane];
            den += exk;
            acc.x = fmaf(exk, zr.x, acc.x);
            acc.y = fmaf(exk, zr.y, acc.y);
        }
    }

    float inv = 1.f / den;
    int j0 = 2 * lane, j1 = 2 * lane + 1;
    float v0 = (acc.x * inv + b[j0] - mean[j0]) * rsqrtf(var[j0] + 1e-5f) * gamma[j0] + beta[j0];
    float v1 = (acc.y * inv + b[j1] - mean[j1]) * rsqrtf(var[j1] + 1e-5f) * gamma[j1] + beta[j1];
    ((float2*)(g_h + (size_t)node * 64))[lane] = make_float2(fmaxf(v0, 0.f), fmaxf(v1, 0.f));
}

// ---------------- structural: influence normalize + max -----------------
__global__ void k_inflnorm() {
    __shared__ float sm[256];
    int i = blockIdx.x * 256 + threadIdx.x;
    float v = 0.f;
    if (i < NN) {
        float dg = g_deg[i];
        v = (dg > 0.f) ? g_infl[i] / fmaxf(dg, 1.f) : 0.f;
        g_infl[i] = v;
    }
    sm[threadIdx.x] = v;
    __syncthreads();
    for (int s = 128; s > 0; s >>= 1) {
        if (threadIdx.x < s) sm[threadIdx.x] = fmaxf(sm[threadIdx.x], sm[threadIdx.x + s]);
        __syncthreads();
    }
    if (threadIdx.x == 0) atomicMax(&g_stat[1], __float_as_uint(sm[0]));
}

// ---------------- K8: SE MLP + output MLP ----------------
__global__ void __launch_bounds__(128) k_out(
        const float* __restrict__ seW1, const float* __restrict__ seb1,
        const float* __restrict__ seW2, const float* __restrict__ seb2,
        const float* __restrict__ oW1, const float* __restrict__ ob1,
        const float* __restrict__ oW2, const float* __restrict__ ob2,
        const float* __restrict__ oW3, const float* __restrict__ ob3,
        float* __restrict__ out) {
    __shared__ float scat[32 * 128];
    __shared__ float ss1[32 * 32];
    __shared__ float so1[32 * 64];
    __shared__ float so2[32 * 32];
    int tid = threadIdx.x;
    int nodeBase = blockIdx.x * 32;
    int g = tid >> 4;
    int l = tid & 15;
    int n0 = nodeBase + g, n1 = n0 + 8, n2 = n0 + 16, n3 = n0 + 24;

#pragma unroll
    for (int i = 0; i < 4; i++) {
        int idx = tid + i * 128;
        int r = idx >> 4, c4 = idx & 15;
        ((float4*)&scat[r * 128])[c4] =
            ((const float4*)(g_h + (size_t)(nodeBase + r) * 64))[c4];
    }

    float degmax  = fmaxf(__uint_as_float(g_stat[0]), 1.f);
    float inflmax = fmaxf(__uint_as_float(g_stat[1]), 1e-12f);

    {
        float nd[4], in[4];
        nd[0] = g_deg[n0] / degmax; in[0] = g_infl[n0] / inflmax;
        nd[1] = g_deg[n1] / degmax; in[1] = g_infl[n1] / inflmax;
        nd[2] = g_deg[n2] / degmax; in[2] = g_infl[n2] / inflmax;
        nd[3] = g_deg[n3] / degmax; in[3] = g_infl[n3] / inflmax;
#pragma unroll
        for (int j = 0; j < 2; j++) {
            int c = 2 * l + j;
            float w0 = seW1[c], w2 = seW1[64 + c], bb = seb1[c];
#pragma unroll
            for (int n = 0; n < 4; n++)
                ss1[(g + 8 * n) * 32 + c] = fmaxf(nd[n] * w0 + in[n] * w2 + bb, 0.f);
        }
    }
    __syncthreads();

    {
        ulonglong2 bb = *(const ulonglong2*)(seb2 + 4 * l);
        unsigned long long A[4][2];
#pragma unroll
        for (int n = 0; n < 4; n++) { A[n][0] = bb.x; A[n][1] = bb.y; }
#pragma unroll 2
        for (int k2 = 0; k2 < 32; k2 += 2) {
            float2 tv[4];
#pragma unroll
            for (int n = 0; n < 4; n++)
                tv[n] = *(const float2*)(ss1 + (g + 8 * n) * 32 + k2);
            ulonglong2 w0 = *(const ulonglong2*)(seW2 + k2 * 64 + 4 * l);
            ulonglong2 w1 = *(const ulonglong2*)(seW2 + (k2 + 1) * 64 + 4 * l);
#pragma unroll
            for (int n = 0; n < 4; n++) {
                unsigned long long a = pk2(tv[n].x), b = pk2(tv[n].y);
                A[n][0] = ffma2(a, w0.x, A[n][0]); A[n][1] = ffma2(a, w0.y, A[n][1]);
                A[n][0] = ffma2(b, w1.x, A[n][0]); A[n][1] = ffma2(b, w1.y, A[n][1]);
            }
        }
#pragma unroll
        for (int n = 0; n < 4; n++) {
            ulonglong2* p = (ulonglong2*)&scat[(g + 8 * n) * 128 + 64 + 4 * l];
            p->x = A[n][0]; p->y = A[n][1];
        }
    }
    __syncthreads();

    {
        ulonglong2 bb = *(const ulonglong2*)(ob1 + 4 * l);
        unsigned long long A[4][2];
#pragma unroll
        for (int n = 0; n < 4; n++) { A[n][0] = bb.x; A[n][1] = bb.y; }
#pragma unroll 2
        for (int k2 = 0; k2 < 128; k2 += 2) {
            float2 cv[4];
#pragma unroll
            for (int n = 0; n < 4; n++)
                cv[n] = *(const float2*)(scat + (g + 8 * n) * 128 + k2);
            ulonglong2 w0 = *(const ulonglong2*)(oW1 + k2 * 64 + 4 * l);
            ulonglong2 w1 = *(const ulonglong2*)(oW1 + (k2 + 1) * 64 + 4 * l);
#pragma unroll
            for (int n = 0; n < 4; n++) {
                unsigned long long a = pk2(cv[n].x), b = pk2(cv[n].y);
                A[n][0] = ffma2(a, w0.x, A[n][0]); A[n][1] = ffma2(a, w0.y, A[n][1]);
                A[n][0] = ffma2(b, w1.x, A[n][0]); A[n][1] = ffma2(b, w1.y, A[n][1]);
            }
        }
#pragma unroll
        for (int n = 0; n < 4; n++)
            st_relu4(so1 + (g + 8 * n) * 64 + 4 * l, A[n][0], A[n][1]);
    }
    __syncthreads();

    {
        unsigned long long bb = *(const unsigned long long*)(ob2 + 2 * l);
        unsigned long long A[4] = {bb, bb, bb, bb};
#pragma unroll 2
        for (int k2 = 0; k2 < 64; k2 += 2) {
            float2 tv[4];
#pragma unroll
            for (int n = 0; n < 4; n++)
                tv[n] = *(const float2*)(so1 + (g + 8 * n) * 64 + k2);
            unsigned long long w0 = *(const unsigned long long*)(oW2 + k2 * 32 + 2 * l);
            unsigned long long w1 = *(const unsigned long long*)(oW2 + (k2 + 1) * 32 + 2 * l);
#pragma unroll
            for (int n = 0; n < 4; n++) {
                A[n] = ffma2(pk2(tv[n].x), w0, A[n]);
                A[n] = ffma2(pk2(tv[n].y), w1, A[n]);
            }
        }
#pragma unroll
        for (int n = 0; n < 4; n++) {
            float2 p = up2(A[n]);
            so2[(g + 8 * n) * 32 + 2 * l]     = fmaxf(p.x, 0.f);
            so2[(g + 8 * n) * 32 + 2 * l + 1] = fmaxf(p.y, 0.f);
        }
    }
    __syncthreads();

    {
        float w0 = oW3[l], w1 = oW3[l + 16];
        float p0 = so2[g * 32 + l] * w0 + so2[g * 32 + l + 16] * w1;
        float p1 = so2[(g + 8) * 32 + l] * w0 + so2[(g + 8) * 32 + l + 16] * w1;
        float p2 = so2[(g + 16) * 32 + l] * w0 + so2[(g + 16) * 32 + l + 16] * w1;
        float p3 = so2[(g + 24) * 32 + l] * w0 + so2[(g + 24) * 32 + l + 16] * w1;
#pragma unroll
        for (int o = 8; o > 0; o >>= 1) {
            p0 += __shfl_down_sync(0xffffffffu, p0, o, 16);
            p1 += __shfl_down_sync(0xffffffffu, p1, o, 16);
            p2 += __shfl_down_sync(0xffffffffu, p2, o, 16);
            p3 += __shfl_down_sync(0xffffffffu, p3, o, 16);
        }
        if (l == 0) {
            float bb = ob3[0];
            out[n0] = 1.f / (1.f + __expf(-(p0 + bb)));
            out[n1] = 1.f / (1.f + __expf(-(p1 + bb)));
            out[n2] = 1.f / (1.f + __expf(-(p2 + bb)));
            out[n3] = 1.f / (1.f + __expf(-(p3 + bb)));
        }
    }
}

// ---------------- launch ----------------
extern "C" void kernel_launch(void* const* d_in, const int* in_sizes, int n_in,
                              void* d_out, int out_size) {
    const float* x    = (const float*)d_in[0];
    const int*   ei   = (const int*)d_in[1];
    const int*   src  = ei;
    const int*   dst  = ei + NE;
    const float* fa_W1  = (const float*)d_in[2];
    const float* fa_b1  = (const float*)d_in[3];
    const float* fa_W2  = (const float*)d_in[4];
    const float* fa_b2  = (const float*)d_in[5];
    const float* proj_W = (const float*)d_in[6];
    const float* proj_b = (const float*)d_in[7];
    const float* gat_W    = (const float*)d_in[8];
    const float* gat_asrc = (const float*)d_in[9];
    const float* gat_adst = (const float*)d_in[10];
    const float* gat_b    = (const float*)d_in[11];
    const float* bn_gamma = (const float*)d_in[12];
    const float* bn_beta  = (const float*)d_in[13];
    const float* bn_mean  = (const float*)d_in[14];
    const float* bn_var   = (const float*)d_in[15];
    const float* se_W1 = (const float*)d_in[16];
    const float* se_b1 = (const float*)d_in[17];
    const float* se_W2 = (const float*)d_in[18];
    const float* se_b2 = (const float*)d_in[19];
    const float* out_W1 = (const float*)d_in[20];
    const float* out_b1 = (const float*)d_in[21];
    const float* out_W2 = (const float*)d_in[22];
    const float* out_b2 = (const float*)d_in[23];
    const float* out_W3 = (const float*)d_in[24];
    const float* out_b3 = (const float*)d_in[25];
    float* out = (float*)d_out;

    // 100000 = 1562*64 + 32
    const int FULL = NN / 64;
    const int TAILBASE = FULL * 64;

    // k_feat<64> as 4th launch: ncu window lands on it
    k_zero<<<(NN + 255) / 256, 256>>>();
    k_hist<<<(NE + 255) / 256, 256>>>(src, dst);
    k_scan1<<<NBLK, SCAN_B>>>();                        // + deg-max fused
    k_feat<64><<<FULL, 128>>>(0, x, fa_W1, fa_b1, fa_W2, fa_b2, proj_W, proj_b);
    k_feat<32><<<1, 128>>>(TAILBASE, x, fa_W1, fa_b1, fa_W2, fa_b2, proj_W, proj_b);
    k_scan2<<<1, 512>>>();
    k_scan3<<<NBLK, SCAN_B>>>();
    k_scatter<<<(NE + 255) / 256, 256>>>(src, dst);     // + influence fused

    for (int l = 0; l < 3; l++) {
        k_zproj<64><<<FULL, 128>>>(0, gat_W + l * H * H, gat_asrc + l * H, gat_adst + l * H);
        k_zproj<32><<<1, 128>>>(TAILBASE, gat_W + l * H * H, gat_asrc + l * H, gat_adst + l * H);
        k_gat<<<(NN * 32 + 255) / 256, 256>>>(gat_b + l * H, bn_gamma + l * H,
                                              bn_beta + l * H, bn_mean + l * H,
                                              bn_var + l * H);
    }

    k_inflnorm<<<(NN + 255) / 256, 256>>>();

    k_out<<<NN / 32, 128>>>(se_W1, se_b1, se_W2, se_b2,
                            out_W1, out_b1, out_W2, out_b2, out_W3, out_b3, out);
}

// round 17
// speedup vs baseline: 1.0386x; 1.0386x over previous
#include <cuda_runtime.h>
#include <math.h>

#define NN 100000
#define NE 1600000
#define D 128
#define H 64
#define SCAN_B 256
#define NBLK ((NN + SCAN_B - 1) / SCAN_B)   // 391

// ---------------- scratch (device globals) ----------------
__device__ float g_h[NN * H];
__device__ float g_z[NN * H];
__device__ float g_zs[NN];
__device__ float g_zd[NN];
__device__ float g_deg[NN];
__device__ float g_infl[NN];
__device__ unsigned int g_stat[2];
__device__ int g_cnt[NN];
__device__ int g_offs[NN + 1];
__device__ int g_cur[NN];
__device__ int g_csr[NE];
__device__ int g_bsum[512];

// ---------------- packed fp32x2 helpers ----------------
__device__ __forceinline__ unsigned long long ffma2(unsigned long long a,
                                                    unsigned long long b,
                                                    unsigned long long c) {
    unsigned long long d;
    asm("fma.rn.f32x2 %0, %1, %2, %3;" : "=l"(d) : "l"(a), "l"(b), "l"(c));
    return d;
}
__device__ __forceinline__ unsigned long long pk2(float x) {
    unsigned long long r;
    asm("mov.b64 %0, {%1, %1};" : "=l"(r) : "f"(x));
    return r;
}
__device__ __forceinline__ float2 up2(unsigned long long v) {
    float2 f;
    asm("mov.b64 {%0, %1}, %2;" : "=f"(f.x), "=f"(f.y) : "l"(v));
    return f;
}
__device__ __forceinline__ void st_relu4(float* p, unsigned long long ax,
                                         unsigned long long ay) {
    float2 u = up2(ax), v = up2(ay);
    p[0] = fmaxf(u.x, 0.f); p[1] = fmaxf(u.y, 0.f);
    p[2] = fmaxf(v.x, 0.f); p[3] = fmaxf(v.y, 0.f);
}

// ---------------- K0: feature attention + projection (R11 version) ------
template <int NODES>
__global__ void __launch_bounds__(128, 4) k_feat(
        int base,
        const float* __restrict__ x,
        const float* __restrict__ W1, const float* __restrict__ b1,
        const float* __restrict__ W2, const float* __restrict__ b2,
        const float* __restrict__ Wp, const float* __restrict__ bp) {
    constexpr int R = NODES / 8;           // rows per thread
    __shared__ float sx[NODES * 128];
    __shared__ float st[NODES * 64];
    int tid = threadIdx.x;
    int nodeBase = base + blockIdx.x * NODES;

    const float4* xg = (const float4*)(x + (size_t)nodeBase * 128);
    float4* sxv = (float4*)sx;
#pragma unroll
    for (int i = 0; i < NODES / 4; i++) sxv[tid + i * 128] = xg[tid + i * 128];
    __syncthreads();

    int g = tid >> 4;
    int l = tid & 15;

    // ---- stage 1: t = relu(x @ W1 + b1)   [K=128 -> O=64]
    {
        ulonglong2 bb = *(const ulonglong2*)(b1 + 4 * l);
        unsigned long long acc[R][2];
#pragma unroll
        for (int n = 0; n < R; n++) { acc[n][0] = bb.x; acc[n][1] = bb.y; }
#pragma unroll 2
        for (int k2 = 0; k2 < 128; k2 += 2) {
            float2 xv[R];
#pragma unroll
            for (int n = 0; n < R; n++)
                xv[n] = *(const float2*)(sx + (g + 8 * n) * 128 + k2);
            ulonglong2 w0 = *(const ulonglong2*)(W1 + k2 * 64 + 4 * l);
            ulonglong2 w1 = *(const ulonglong2*)(W1 + (k2 + 1) * 64 + 4 * l);
#pragma unroll
            for (int n = 0; n < R; n++) {
                unsigned long long a = pk2(xv[n].x), b = pk2(xv[n].y);
                acc[n][0] = ffma2(a, w0.x, acc[n][0]);
                acc[n][1] = ffma2(a, w0.y, acc[n][1]);
                acc[n][0] = ffma2(b, w1.x, acc[n][0]);
                acc[n][1] = ffma2(b, w1.y, acc[n][1]);
            }
        }
#pragma unroll
        for (int n = 0; n < R; n++)
            st_relu4(st + (g + 8 * n) * 64 + 4 * l, acc[n][0], acc[n][1]);
    }
    __syncthreads();

    // ---- stage 2: a = t @ W2 + b2  [K=64 -> O=128]; x *= sigmoid(a)
#pragma unroll
    for (int c = 0; c < R; c += 4) {
        ulonglong2 c0 = *(const ulonglong2*)(b2 + 8 * l);
        ulonglong2 c1 = *(const ulonglong2*)(b2 + 8 * l + 4);
        unsigned long long A[4][4];
#pragma unroll
        for (int n = 0; n < 4; n++) {
            A[n][0] = c0.x; A[n][1] = c0.y; A[n][2] = c1.x; A[n][3] = c1.y;
        }
#pragma unroll 2
        for (int k2 = 0; k2 < 64; k2 += 2) {
            float2 tv[4];
#pragma unroll
            for (int n = 0; n < 4; n++)
                tv[n] = *(const float2*)(st + (g + 8 * (c + n)) * 64 + k2);
            ulonglong2 wa0 = *(const ulonglong2*)(W2 + k2 * 128 + 8 * l);
            ulonglong2 wb0 = *(const ulonglong2*)(W2 + k2 * 128 + 8 * l + 4);
            ulonglong2 wa1 = *(const ulonglong2*)(W2 + (k2 + 1) * 128 + 8 * l);
            ulonglong2 wb1 = *(const ulonglong2*)(W2 + (k2 + 1) * 128 + 8 * l + 4);
#pragma unroll
            for (int n = 0; n < 4; n++) {
                unsigned long long a = pk2(tv[n].x), b = pk2(tv[n].y);
                A[n][0] = ffma2(a, wa0.x, A[n][0]); A[n][1] = ffma2(a, wa0.y, A[n][1]);
                A[n][2] = ffma2(a, wb0.x, A[n][2]); A[n][3] = ffma2(a, wb0.y, A[n][3]);
                A[n][0] = ffma2(b, wa1.x, A[n][0]); A[n][1] = ffma2(b, wa1.y, A[n][1]);
                A[n][2] = ffma2(b, wb1.x, A[n][2]); A[n][3] = ffma2(b, wb1.y, A[n][3]);
            }
        }
#pragma unroll
        for (int n = 0; n < 4; n++) {
            float* row = sx + (g + 8 * (c + n)) * 128 + 8 * l;
            float av[8];
            float2 p;
            p = up2(A[n][0]); av[0] = p.x; av[1] = p.y;
            p = up2(A[n][1]); av[2] = p.x; av[3] = p.y;
            p = up2(A[n][2]); av[4] = p.x; av[5] = p.y;
            p = up2(A[n][3]); av[6] = p.x; av[7] = p.y;
#pragma unroll
            for (int j = 0; j < 8; j++) row[j] *= 1.f / (1.f + __expf(-av[j]));
        }
    }
    __syncthreads();

    // ---- stage 3: h = xf @ Wp + bp  [K=128 -> O=64]
    {
        ulonglong2 bb = *(const ulonglong2*)(bp + 4 * l);
        unsigned long long acc[R][2];
#pragma unroll
        for (int n = 0; n < R; n++) { acc[n][0] = bb.x; acc[n][1] = bb.y; }
#pragma unroll 2
        for (int k2 = 0; k2 < 128; k2 += 2) {
            float2 xv[R];
#pragma unroll
            for (int n = 0; n < R; n++)
                xv[n] = *(const float2*)(sx + (g + 8 * n) * 128 + k2);
            ulonglong2 w0 = *(const ulonglong2*)(Wp + k2 * 64 + 4 * l);
            ulonglong2 w1 = *(const ulonglong2*)(Wp + (k2 + 1) * 64 + 4 * l);
#pragma unroll
            for (int n = 0; n < R; n++) {
                unsigned long long a = pk2(xv[n].x), b = pk2(xv[n].y);
                acc[n][0] = ffma2(a, w0.x, acc[n][0]);
                acc[n][1] = ffma2(a, w0.y, acc[n][1]);
                acc[n][0] = ffma2(b, w1.x, acc[n][0]);
                acc[n][1] = ffma2(b, w1.y, acc[n][1]);
            }
        }
#pragma unroll
        for (int n = 0; n < R; n++) {
            ulonglong2* h = (ulonglong2*)(g_h + (size_t)(nodeBase + g + 8 * n) * 64 + 4 * l);
            h->x = acc[n][0]; h->y = acc[n][1];
        }
    }
}

// ---------------- CSR build ----------------
__global__ void k_zero() {
    int i = blockIdx.x * blockDim.x + threadIdx.x;
    if (i < NN) { g_cnt[i] = 0; g_deg[i] = 0.f; g_infl[i] = 0.f; }
    if (i < 2) g_stat[i] = 0u;
}
__global__ void k_hist(const int* __restrict__ src, const int* __restrict__ dst) {
    int i = blockIdx.x * blockDim.x + threadIdx.x;
    if (i >= NE) return;
    atomicAdd(&g_cnt[dst[i]], 1);
    atomicAdd(&g_deg[src[i]], 1.f);
}
__global__ void k_scan1() {
    __shared__ int sh[SCAN_B];
    __shared__ float sm[SCAN_B];
    int i = blockIdx.x * SCAN_B + threadIdx.x;
    int v = (i < NN) ? g_cnt[i] : 0;
    sm[threadIdx.x] = (i < NN) ? g_deg[i] : 0.f;
    sh[threadIdx.x] = v;
    __syncthreads();
    for (int off = 1; off < SCAN_B; off <<= 1) {
        int add = (threadIdx.x >= off) ? sh[threadIdx.x - off] : 0;
        __syncthreads();
        sh[threadIdx.x] += add;
        __syncthreads();
    }
    if (i < NN) g_offs[i + 1] = sh[threadIdx.x];
    if (threadIdx.x == SCAN_B - 1) g_bsum[blockIdx.x] = sh[threadIdx.x];
    for (int s = 128; s > 0; s >>= 1) {
        if (threadIdx.x < s) sm[threadIdx.x] = fmaxf(sm[threadIdx.x], sm[threadIdx.x + s]);
        __syncthreads();
    }
    if (threadIdx.x == 0) atomicMax(&g_stat[0], __float_as_uint(sm[0]));
}
__global__ void k_scan2() {
    __shared__ int sh[512];
    int t = threadIdx.x;
    sh[t] = (t < NBLK) ? g_bsum[t] : 0;
    __syncthreads();
    for (int off = 1; off < 512; off <<= 1) {
        int add = (t >= off) ? sh[t - off] : 0;
        __syncthreads();
        sh[t] += add;
        __syncthreads();
    }
    if (t < NBLK) g_bsum[t] = sh[t];
}
__global__ void k_scan3() {
    int i = blockIdx.x * SCAN_B + threadIdx.x;
    if (i >= NN) return;
    int blk = blockIdx.x;
    int pre = (blk > 0) ? g_bsum[blk - 1] : 0;
    int inc = g_offs[i + 1] + pre;
    g_offs[i + 1] = inc;
    g_cur[i] = inc - g_cnt[i];
    if (i == 0) g_offs[0] = 0;
}
__global__ void k_scatter(const int* __restrict__ src, const int* __restrict__ dst) {
    int i = blockIdx.x * blockDim.x + threadIdx.x;
    if (i >= NE) return;
    int s = src[i];
    int d = dst[i];
    int pos = atomicAdd(&g_cur[d], 1);
    g_csr[pos] = s;
    atomicAdd(&g_infl[s], g_deg[d]);
}

// ---------------- K1: z = h @ W, zs, zd (R12 32-node version) -----------
__global__ void __launch_bounds__(128) k_zproj(
        const float* __restrict__ W,
        const float* __restrict__ asrc,
        const float* __restrict__ adst) {
    __shared__ float sh[32 * 64];
    __shared__ float sa[64], sd[64];
    int tid = threadIdx.x;
    int nodeBase = blockIdx.x * 32;
    const float4* hg = (const float4*)(g_h + (size_t)nodeBase * 64);
#pragma unroll
    for (int i = 0; i < 4; i++) ((float4*)sh)[tid + i * 128] = hg[tid + i * 128];
    if (tid < 64) { sa[tid] = asrc[tid]; sd[tid] = adst[tid]; }
    __syncthreads();

    int g = tid >> 4;
    int l = tid & 15;
    unsigned long long acc[4][2];
#pragma unroll
    for (int n = 0; n < 4; n++) { acc[n][0] = 0; acc[n][1] = 0; }
#pragma unroll 2
    for (int k2 = 0; k2 < 64; k2 += 2) {
        float2 hv[4];
#pragma unroll
        for (int n = 0; n < 4; n++)
            hv[n] = *(const float2*)(sh + (g + 8 * n) * 64 + k2);
        ulonglong2 w0 = *(const ulonglong2*)(W + k2 * 64 + 4 * l);
        ulonglong2 w1 = *(const ulonglong2*)(W + (k2 + 1) * 64 + 4 * l);
#pragma unroll
        for (int n = 0; n < 4; n++) {
            unsigned long long a = pk2(hv[n].x), b = pk2(hv[n].y);
            acc[n][0] = ffma2(a, w0.x, acc[n][0]);
            acc[n][1] = ffma2(a, w0.y, acc[n][1]);
            acc[n][0] = ffma2(b, w1.x, acc[n][0]);
            acc[n][1] = ffma2(b, w1.y, acc[n][1]);
        }
    }
    int c = 4 * l;
    float4 va = make_float4(sa[c], sa[c + 1], sa[c + 2], sa[c + 3]);
    float4 vd = make_float4(sd[c], sd[c + 1], sd[c + 2], sd[c + 3]);
    float s[4], dsum[4];
#pragma unroll
    for (int n = 0; n < 4; n++) {
        int node = nodeBase + g + 8 * n;
        ulonglong2* z = (ulonglong2*)(g_z + (size_t)node * 64 + 4 * l);
        z->x = acc[n][0]; z->y = acc[n][1];
        float2 p = up2(acc[n][0]), q = up2(acc[n][1]);
        s[n]    = p.x * va.x + p.y * va.y + q.x * va.z + q.y * va.w;
        dsum[n] = p.x * vd.x + p.y * vd.y + q.x * vd.z + q.y * vd.w;
    }
#pragma unroll
    for (int o = 8; o > 0; o >>= 1) {
#pragma unroll
        for (int n = 0; n < 4; n++) {
            s[n]    += __shfl_down_sync(0xffffffffu, s[n], o, 16);
            dsum[n] += __shfl_down_sync(0xffffffffu, dsum[n], o, 16);
        }
    }
    if (l == 0) {
#pragma unroll
        for (int n = 0; n < 4; n++) {
            int node = nodeBase + g + 8 * n;
            g_zs[node] = s[n];
            g_zd[node] = dsum[n];
        }
    }
}

// ---------------- K2: fused GAT layer — single pass, rolled loop --------
__global__ void k_gat(const float* __restrict__ b, const float* __restrict__ gamma,
                      const float* __restrict__ beta, const float* __restrict__ mean,
                      const float* __restrict__ var) {
    int node = (blockIdx.x * blockDim.x + threadIdx.x) >> 5;
    int lane = threadIdx.x & 31;
    if (node >= NN) return;

    int beg = g_offs[node];
    int end = g_offs[node + 1];
    float zdn = g_zd[node];

    float es = g_zs[node] + zdn;
    es = (es > 0.f) ? es : 0.2f * es;
    float exs = __expf(es);
    float den = exs;
    float2 zv = ((const float2*)(g_z + (size_t)node * 64))[lane];
    float2 acc = make_float2(exs * zv.x, exs * zv.y);

    for (int base = beg; base < end; base += 32) {
        int j = base + lane;
        float ex = 0.f;
        int s = 0;
        if (j < end) {
            s = g_csr[j];
            float e = g_zs[s] + zdn;
            e = (e > 0.f) ? e : 0.2f * e;
            ex = __expf(e);
        }
        int nk = min(32, end - base);
        for (int k = 0; k < nk; k++) {
            float exk = __shfl_sync(0xffffffffu, ex, k);
            int sk = __shfl_sync(0xffffffffu, s, k);
            float2 zr = ((const float2*)(g_z + (size_t)sk * 64))[lane];
            den += exk;
            acc.x = fmaf(exk, zr.x, acc.x);
            acc.y = fmaf(exk, zr.y, acc.y);
        }
    }

    float inv = 1.f / den;
    int j0 = 2 * lane, j1 = 2 * lane + 1;
    float v0 = (acc.x * inv + b[j0] - mean[j0]) * rsqrtf(var[j0] + 1e-5f) * gamma[j0] + beta[j0];
    float v1 = (acc.y * inv + b[j1] - mean[j1]) * rsqrtf(var[j1] + 1e-5f) * gamma[j1] + beta[j1];
    ((float2*)(g_h + (size_t)node * 64))[lane] = make_float2(fmaxf(v0, 0.f), fmaxf(v1, 0.f));
}

// ---------------- structural: influence normalize + max -----------------
__global__ void k_inflnorm() {
    __shared__ float sm[256];
    int i = blockIdx.x * 256 + threadIdx.x;
    float v = 0.f;
    if (i < NN) {
        float dg = g_deg[i];
        v = (dg > 0.f) ? g_infl[i] / fmaxf(dg, 1.f) : 0.f;
        g_infl[i] = v;
    }
    sm[threadIdx.x] = v;
    __syncthreads();
    for (int s = 128; s > 0; s >>= 1) {
        if (threadIdx.x < s) sm[threadIdx.x] = fmaxf(sm[threadIdx.x], sm[threadIdx.x + s]);
        __syncthreads();
    }
    if (threadIdx.x == 0) atomicMax(&g_stat[1], __float_as_uint(sm[0]));
}

// ---------------- K8: SE MLP + output MLP ----------------
__global__ void __launch_bounds__(128) k_out(
        const float* __restrict__ seW1, const float* __restrict__ seb1,
        const float* __restrict__ seW2, const float* __restrict__ seb2,
        const float* __restrict__ oW1, const float* __restrict__ ob1,
        const float* __restrict__ oW2, const float* __restrict__ ob2,
        const float* __restrict__ oW3, const float* __restrict__ ob3,
        float* __restrict__ out) {
    __shared__ float scat[32 * 128];
    __shared__ float ss1[32 * 32];
    __shared__ float so1[32 * 64];
    __shared__ float so2[32 * 32];
    int tid = threadIdx.x;
    int nodeBase = blockIdx.x * 32;
    int g = tid >> 4;
    int l = tid & 15;
    int n0 = nodeBase + g, n1 = n0 + 8, n2 = n0 + 16, n3 = n0 + 24;

#pragma unroll
    for (int i = 0; i < 4; i++) {
        int idx = tid + i * 128;
        int r = idx >> 4, c4 = idx & 15;
        ((float4*)&scat[r * 128])[c4] =
            ((const float4*)(g_h + (size_t)(nodeBase + r) * 64))[c4];
    }

    float degmax  = fmaxf(__uint_as_float(g_stat[0]), 1.f);
    float inflmax = fmaxf(__uint_as_float(g_stat[1]), 1e-12f);

    {
        float nd[4], in[4];
        nd[0] = g_deg[n0] / degmax; in[0] = g_infl[n0] / inflmax;
        nd[1] = g_deg[n1] / degmax; in[1] = g_infl[n1] / inflmax;
        nd[2] = g_deg[n2] / degmax; in[2] = g_infl[n2] / inflmax;
        nd[3] = g_deg[n3] / degmax; in[3] = g_infl[n3] / inflmax;
#pragma unroll
        for (int j = 0; j < 2; j++) {
            int c = 2 * l + j;
            float w0 = seW1[c], w2 = seW1[64 + c], bb = seb1[c];
#pragma unroll
            for (int n = 0; n < 4; n++)
                ss1[(g + 8 * n) * 32 + c] = fmaxf(nd[n] * w0 + in[n] * w2 + bb, 0.f);
        }
    }
    __syncthreads();

    {
        ulonglong2 bb = *(const ulonglong2*)(seb2 + 4 * l);
        unsigned long long A[4][2];
#pragma unroll
        for (int n = 0; n < 4; n++) { A[n][0] = bb.x; A[n][1] = bb.y; }
#pragma unroll 2
        for (int k2 = 0; k2 < 32; k2 += 2) {
            float2 tv[4];
#pragma unroll
            for (int n = 0; n < 4; n++)
                tv[n] = *(const float2*)(ss1 + (g + 8 * n) * 32 + k2);
            ulonglong2 w0 = *(const ulonglong2*)(seW2 + k2 * 64 + 4 * l);
            ulonglong2 w1 = *(const ulonglong2*)(seW2 + (k2 + 1) * 64 + 4 * l);
#pragma unroll
            for (int n = 0; n < 4; n++) {
                unsigned long long a = pk2(tv[n].x), b = pk2(tv[n].y);
                A[n][0] = ffma2(a, w0.x, A[n][0]); A[n][1] = ffma2(a, w0.y, A[n][1]);
                A[n][0] = ffma2(b, w1.x, A[n][0]); A[n][1] = ffma2(b, w1.y, A[n][1]);
            }
        }
#pragma unroll
        for (int n = 0; n < 4; n++) {
            ulonglong2* p = (ulonglong2*)&scat[(g + 8 * n) * 128 + 64 + 4 * l];
            p->x = A[n][0]; p->y = A[n][1];
        }
    }
    __syncthreads();

    {
        ulonglong2 bb = *(const ulonglong2*)(ob1 + 4 * l);
        unsigned long long A[4][2];
#pragma unroll
        for (int n = 0; n < 4; n++) { A[n][0] = bb.x; A[n][1] = bb.y; }
#pragma unroll 2
        for (int k2 = 0; k2 < 128; k2 += 2) {
            float2 cv[4];
#pragma unroll
            for (int n = 0; n < 4; n++)
                cv[n] = *(const float2*)(scat + (g + 8 * n) * 128 + k2);
            ulonglong2 w0 = *(const ulonglong2*)(oW1 + k2 * 64 + 4 * l);
            ulonglong2 w1 = *(const ulonglong2*)(oW1 + (k2 + 1) * 64 + 4 * l);
#pragma unroll
            for (int n = 0; n < 4; n++) {
                unsigned long long a = pk2(cv[n].x), b = pk2(cv[n].y);
                A[n][0] = ffma2(a, w0.x, A[n][0]); A[n][1] = ffma2(a, w0.y, A[n][1]);
                A[n][0] = ffma2(b, w1.x, A[n][0]); A[n][1] = ffma2(b, w1.y, A[n][1]);
            }
        }
#pragma unroll
        for (int n = 0; n < 4; n++)
            st_relu4(so1 + (g + 8 * n) * 64 + 4 * l, A[n][0], A[n][1]);
    }
    __syncthreads();

    {
        unsigned long long bb = *(const unsigned long long*)(ob2 + 2 * l);
        unsigned long long A[4] = {bb, bb, bb, bb};
#pragma unroll 2
        for (int k2 = 0; k2 < 64; k2 += 2) {
            float2 tv[4];
#pragma unroll
            for (int n = 0; n < 4; n++)
                tv[n] = *(const float2*)(so1 + (g + 8 * n) * 64 + k2);
            unsigned long long w0 = *(const unsigned long long*)(oW2 + k2 * 32 + 2 * l);
            unsigned long long w1 = *(const unsigned long long*)(oW2 + (k2 + 1) * 32 + 2 * l);
#pragma unroll
            for (int n = 0; n < 4; n++) {
                A[n] = ffma2(pk2(tv[n].x), w0, A[n]);
                A[n] = ffma2(pk2(tv[n].y), w1, A[n]);
            }
        }
#pragma unroll
        for (int n = 0; n < 4; n++) {
            float2 p = up2(A[n]);
            so2[(g + 8 * n) * 32 + 2 * l]     = fmaxf(p.x, 0.f);
            so2[(g + 8 * n) * 32 + 2 * l + 1] = fmaxf(p.y, 0.f);
        }
    }
    __syncthreads();

    {
        float w0 = oW3[l], w1 = oW3[l + 16];
        float p0 = so2[g * 32 + l] * w0 + so2[g * 32 + l + 16] * w1;
        float p1 = so2[(g + 8) * 32 + l] * w0 + so2[(g + 8) * 32 + l + 16] * w1;
        float p2 = so2[(g + 16) * 32 + l] * w0 + so2[(g + 16) * 32 + l + 16] * w1;
        float p3 = so2[(g + 24) * 32 + l] * w0 + so2[(g + 24) * 32 + l + 16] * w1;
#pragma unroll
        for (int o = 8; o > 0; o >>= 1) {
            p0 += __shfl_down_sync(0xffffffffu, p0, o, 16);
            p1 += __shfl_down_sync(0xffffffffu, p1, o, 16);
            p2 += __shfl_down_sync(0xffffffffu, p2, o, 16);
            p3 += __shfl_down_sync(0xffffffffu, p3, o, 16);
        }
        if (l == 0) {
            float bb = ob3[0];
            out[n0] = 1.f / (1.f + __expf(-(p0 + bb)));
            out[n1] = 1.f / (1.f + __expf(-(p1 + bb)));
            out[n2] = 1.f / (1.f + __expf(-(p2 + bb)));
            out[n3] = 1.f / (1.f + __expf(-(p3 + bb)));
        }
    }
}

// ---------------- launch ----------------
extern "C" void kernel_launch(void* const* d_in, const int* in_sizes, int n_in,
                              void* d_out, int out_size) {
    const float* x    = (const float*)d_in[0];
    const int*   ei   = (const int*)d_in[1];
    const int*   src  = ei;
    const int*   dst  = ei + NE;
    const float* fa_W1  = (const float*)d_in[2];
    const float* fa_b1  = (const float*)d_in[3];
    const float* fa_W2  = (const float*)d_in[4];
    const float* fa_b2  = (const float*)d_in[5];
    const float* proj_W = (const float*)d_in[6];
    const float* proj_b = (const float*)d_in[7];
    const float* gat_W    = (const float*)d_in[8];
    const float* gat_asrc = (const float*)d_in[9];
    const float* gat_adst = (const float*)d_in[10];
    const float* gat_b    = (const float*)d_in[11];
    const float* bn_gamma = (const float*)d_in[12];
    const float* bn_beta  = (const float*)d_in[13];
    const float* bn_mean  = (const float*)d_in[14];
    const float* bn_var   = (const float*)d_in[15];
    const float* se_W1 = (const float*)d_in[16];
    const float* se_b1 = (const float*)d_in[17];
    const float* se_W2 = (const float*)d_in[18];
    const float* se_b2 = (const float*)d_in[19];
    const float* out_W1 = (const float*)d_in[20];
    const float* out_b1 = (const float*)d_in[21];
    const float* out_W2 = (const float*)d_in[22];
    const float* out_b2 = (const float*)d_in[23];
    const float* out_W3 = (const float*)d_in[24];
    const float* out_b3 = (const float*)d_in[25];
    float* out = (float*)d_out;

    // 100000 = 1562*64 + 32
    const int FULL = NN / 64;
    const int TAILBASE = FULL * 64;

    // k_feat<64> as 4th launch: ncu window lands on it
    k_zero<<<(NN + 255) / 256, 256>>>();
    k_hist<<<(NE + 255) / 256, 256>>>(src, dst);
    k_scan1<<<NBLK, SCAN_B>>>();                        // + deg-max fused
    k_feat<64><<<FULL, 128>>>(0, x, fa_W1, fa_b1, fa_W2, fa_b2, proj_W, proj_b);
    k_feat<32><<<1, 128>>>(TAILBASE, x, fa_W1, fa_b1, fa_W2, fa_b2, proj_W, proj_b);
    k_scan2<<<1, 512>>>();
    k_scan3<<<NBLK, SCAN_B>>>();
    k_scatter<<<(NE + 255) / 256, 256>>>(src, dst);     // + influence fused

    for (int l = 0; l < 3; l++) {
        k_zproj<<<NN / 32, 128>>>(gat_W + l * H * H, gat_asrc + l * H, gat_adst + l * H);
        k_gat<<<(NN * 32 + 255) / 256, 256>>>(gat_b + l * H, bn_gamma + l * H,
                                              bn_beta + l * H, bn_mean + l * H,
                                              bn_var + l * H);
    }

    k_inflnorm<<<(NN + 255) / 256, 256>>>();

    k_out<<<NN / 32, 128>>>(se_W1, se_b1, se_W2, se_b2,
                            out_W1, out_b1, out_W2, out_b2, out_W3, out_b3, out);
}